// round 5
// baseline (speedup 1.0000x reference)
#include <cuda_runtime.h>
#include <cstdint>

#define Bb 32
#define Dd 20
#define Ll 4096
#define Kk 1000
#define Nn (Bb*Ll)
#define NDLs (Bb*Dd*Ll)
#define ROWW 52                   // words per smem code row: 24 h + 24 l + 4 pad
#define SMEM_BYTES (1024*ROWW*4)  // 212992
#define NUNITS (Nn/16)            // 8192 m16 tiles
#define NWARPS (148*8)
#define FINB (Nn/256)

__device__ int   g_idx[Nn];
__device__ int   g_work;
__device__ float g_kl;
__device__ int   g_hist[Kk];
__device__ int   g_done;

__device__ __forceinline__ uint32_t tf32h(float v){
  uint32_t r; asm("cvt.rna.tf32.f32 %0, %1;" : "=r"(r) : "f"(v)); return r;
}
__device__ __forceinline__ void mma_tf32(float* d, const uint32_t* a, const uint32_t* b, const float* c){
  asm volatile("mma.sync.aligned.m16n8k8.row.col.f32.tf32.tf32.f32 "
    "{%0,%1,%2,%3},{%4,%5,%6,%7},{%8,%9},{%10,%11,%12,%13};"
    : "=f"(d[0]),"=f"(d[1]),"=f"(d[2]),"=f"(d[3])
    : "r"(a[0]),"r"(a[1]),"r"(a[2]),"r"(a[3]), "r"(b[0]),"r"(b[1]),
      "f"(c[0]),"f"(c[1]),"f"(c[2]),"f"(c[3]));
}
__device__ __forceinline__ void lds64(uint32_t& x, uint32_t& y, uint32_t a){
  asm volatile("ld.shared.v2.b32 {%0,%1},[%2];" : "=r"(x), "=r"(y) : "r"(a));
}
__device__ __forceinline__ uint32_t smem_u32(const void* p){
  uint32_t a; asm("{ .reg .u64 t; cvta.to.shared.u64 t, %1; cvt.u32.u64 %0, t; }" : "=r"(a) : "l"(p));
  return a;
}
// position of k within permuted 8-chunk: [k0,k4,k1,k5,k2,k6,k3,k7]
__device__ __forceinline__ int pperm(int k){
  int km = k & 7; return (k & ~7) + ((km < 4) ? 2*km : 2*(km-4)+1);
}

__global__ void __launch_bounds__(256,1) vq_main(const float* __restrict__ x,
                                                 const float* __restrict__ emb){
  extern __shared__ float sm[];
  const uint32_t sbase = smem_u32(sm);
  const int tid = threadIdx.x, lane = tid & 31;
  const int q = lane & 3, r0 = lane >> 2;

  // build codebook h/l tf32 splits in smem
  for (int k = tid; k < 1024; k += 256){
    float e[Dd]; float nh;
    if (k < Kk){
      float s = 0.f;
      #pragma unroll
      for (int d = 0; d < Dd; d++){ e[d] = __ldg(emb + k*Dd + d); s = fmaf(e[d], e[d], s); }
      nh = -0.5f*s;
    } else {
      #pragma unroll
      for (int d = 0; d < Dd; d++) e[d] = 0.f;
      nh = -1e30f;
    }
    uint32_t* row = (uint32_t*)(sm + k*ROWW);
    #pragma unroll
    for (int kk = 0; kk < 24; kk++){
      float v = (kk < Dd) ? e[kk] : ((kk == Dd) ? nh : 0.f);
      uint32_t h = tf32h(v);
      float lres = v - __uint_as_float(h);
      row[pperm(kk)]      = h;
      row[24 + pperm(kk)] = tf32h(lres);
    }
  }
  __syncthreads();

  int u = blockIdx.x*8 + (tid >> 5);
  while (u < NUNITS){
    // A fragments: rows r0, r0+8 of this 16-point tile; k = q + 4m, m=0..5
    uint32_t ah[3][4], al[3][4];
    {
      const int n0 = u*16 + r0, n1 = n0 + 8;
      const float* p0 = x + (size_t)(n0 >> 12)*(Dd*Ll) + (n0 & (Ll-1));
      const float* p1 = x + (size_t)(n1 >> 12)*(Dd*Ll) + (n1 & (Ll-1));
      #pragma unroll
      for (int m = 0; m < 6; m++){
        const int k = q + 4*m;
        float v0 = (k < Dd) ? __ldg(p0 + k*Ll) : ((k == Dd) ? 1.f : 0.f);
        float v1 = (k < Dd) ? __ldg(p1 + k*Ll) : ((k == Dd) ? 1.f : 0.f);
        const int c = m >> 1, hi = (m & 1) ? 2 : 0;
        uint32_t h0 = tf32h(v0), h1 = tf32h(v1);
        ah[c][hi] = h0; ah[c][hi+1] = h1;
        al[c][hi]   = tf32h(v0 - __uint_as_float(h0));
        al[c][hi+1] = tf32h(v1 - __uint_as_float(h1));
      }
    }

    float best0 = -3.4e38f, best1 = -3.4e38f;
    int   idx0 = 0, idx1 = 0;
    const float z[4] = {0.f, 0.f, 0.f, 0.f};

    #pragma unroll 1
    for (int nb = 0; nb < 128; nb++){
      const uint32_t rb = sbase + ((nb*8 + r0)*ROWW + 2*q)*4;
      uint32_t bh[3][2], bl[3][2];
      #pragma unroll
      for (int c = 0; c < 3; c++){
        lds64(bh[c][0], bh[c][1], rb + c*32);
        lds64(bl[c][0], bl[c][1], rb + 96 + c*32);
      }
      float d4[4];
      mma_tf32(d4, ah[0], bh[0], z);
      mma_tf32(d4, ah[1], bh[1], d4);
      mma_tf32(d4, ah[2], bh[2], d4);
      mma_tf32(d4, ah[0], bl[0], d4);
      mma_tf32(d4, ah[1], bl[1], d4);
      mma_tf32(d4, ah[2], bl[2], d4);
      mma_tf32(d4, al[0], bh[0], d4);
      mma_tf32(d4, al[1], bh[1], d4);
      mma_tf32(d4, al[2], bh[2], d4);

      const int c0 = nb*8 + 2*q;
      if (d4[0] > best0){ best0 = d4[0]; idx0 = c0; }
      if (d4[1] > best0){ best0 = d4[1]; idx0 = c0+1; }
      if (d4[2] > best1){ best1 = d4[2]; idx1 = c0; }
      if (d4[3] > best1){ best1 = d4[3]; idx1 = c0+1; }
    }

    // reduce across the 4 lanes sharing each row
    #pragma unroll
    for (int off = 1; off <= 2; off <<= 1){
      float s0 = __shfl_xor_sync(0xFFFFFFFFu, best0, off);
      int   i0 = __shfl_xor_sync(0xFFFFFFFFu, idx0,  off);
      if (s0 > best0 || (s0 == best0 && i0 < idx0)){ best0 = s0; idx0 = i0; }
      float s1 = __shfl_xor_sync(0xFFFFFFFFu, best1, off);
      int   i1 = __shfl_xor_sync(0xFFFFFFFFu, idx1,  off);
      if (s1 > best1 || (s1 == best1 && i1 < idx1)){ best1 = s1; idx1 = i1; }
    }
    if (q == 0){
      g_idx[u*16 + r0]     = idx0;
      g_idx[u*16 + r0 + 8] = idx1;
    }

    if (lane == 0) u = NWARPS + atomicAdd(&g_work, 1);
    u = __shfl_sync(0xFFFFFFFFu, u, 0);
  }
}

__global__ void __launch_bounds__(256) vq_fin(const float* __restrict__ x,
                                              const float* __restrict__ emb,
                                              float* __restrict__ out, int out_size){
  __shared__ int sh[Kk];
  __shared__ float swr[8];
  __shared__ int slast;
  const int tid = threadIdx.x;
  for (int i = tid; i < Kk; i += 256) sh[i] = 0;
  __syncthreads();

  const int n = blockIdx.x*256 + tid;
  const int code = g_idx[n];

  const int bb = n >> 12, l = n & (Ll-1);
  const float* xp = x + (size_t)bb*(Dd*Ll) + l;
  float xv[Dd], qv[Dd];
  #pragma unroll
  for (int d = 0; d < Dd; d++){ xv[d] = __ldg(xp + d*Ll); qv[d] = __ldg(emb + code*Dd + d); }
  float* op = out + (size_t)bb*(Dd*Ll) + l;
  #pragma unroll
  for (int d = 0; d < Dd; d++) op[d*Ll] = xv[d] + (qv[d] - xv[d]);
  atomicAdd(&sh[code], 1);

  float mx = xv[0], mq = qv[0];
  #pragma unroll
  for (int d = 1; d < Dd; d++){ mx = fmaxf(mx, xv[d]); mq = fmaxf(mq, qv[d]); }
  float Sx = 0.f, Sq = 0.f, A = 0.f, Cr = 0.f;
  #pragma unroll
  for (int d = 0; d < Dd; d++){
    float xs = xv[d] - mx;
    float ex = __expf(xs), eq = __expf(qv[d] - mq);
    Sx += ex; Sq += eq;
    A  = fmaf(ex, xs, A);
    Cr = fmaf(ex, eq, Cr);
  }
  float kl = A/Sx - __logf(Sx) - Cr/(Sx*Sq);

  #pragma unroll
  for (int off = 16; off; off >>= 1) kl += __shfl_xor_sync(0xFFFFFFFFu, kl, off);
  if ((tid & 31) == 0) swr[tid >> 5] = kl;
  __syncthreads();
  if (tid == 0){
    float s = 0.f;
    #pragma unroll
    for (int i = 0; i < 8; i++) s += swr[i];
    atomicAdd(&g_kl, s);
  }
  for (int i = tid; i < Kk; i += 256){ int c = sh[i]; if (c) atomicAdd(&g_hist[i], c); }

  __threadfence();
  __syncthreads();
  if (tid == 0) slast = (atomicAdd(&g_done, 1) == FINB - 1);
  __syncthreads();
  if (slast){
    float s = 0.f;
    for (int k = tid; k < Kk; k += 256){
      float a = (float)(*(volatile int*)&g_hist[k]) * (1.f/(float)Nn);
      s += a * logf(a + 1e-10f);
      g_hist[k] = 0;
    }
    #pragma unroll
    for (int off = 16; off; off >>= 1) s += __shfl_xor_sync(0xFFFFFFFFu, s, off);
    if ((tid & 31) == 0) swr[tid >> 5] = s;
    __syncthreads();
    if (tid == 0){
      float t = 0.f;
      #pragma unroll
      for (int i = 0; i < 8; i++) t += swr[i];
      if (out_size >= NDLs + 2){
        out[NDLs]     = 0.1f * ((*(volatile float*)&g_kl) / (float)Bb);
        out[NDLs + 1] = expf(-t);
      }
      g_kl = 0.f; g_done = 0; g_work = 0;
    }
  }
}

extern "C" void kernel_launch(void* const* d_in, const int* in_sizes, int n_in,
                              void* d_out, int out_size){
  const float* x   = (const float*)d_in[0];
  const float* emb = (const float*)d_in[1];
  float* out = (float*)d_out;
  cudaFuncSetAttribute(vq_main, cudaFuncAttributeMaxDynamicSharedMemorySize, SMEM_BYTES);
  vq_main<<<148, 256, SMEM_BYTES>>>(x, emb);
  vq_fin<<<FINB, 256>>>(x, emb, out, out_size);
}

// round 6
// speedup vs baseline: 1.1782x; 1.1782x over previous
#include <cuda_runtime.h>
#include <cstdint>

#define Bb 32
#define Dd 20
#define Ll 4096
#define Kk 1000
#define Nn (Bb*Ll)
#define NDLs (Bb*Dd*Ll)
#define ROWW 52                   // words per smem code row: 24 h + 24 l + 4 pad
#define SMEM_BYTES (1024*ROWW*4)  // 212992
#define NUNITS (Nn/16)            // 8192 m16 tiles
#define NWARPS (148*16)
#define FINB (Nn/256)

__device__ int   g_idx[Nn];
__device__ int   g_work;
__device__ float g_kl;
__device__ int   g_hist[Kk];
__device__ int   g_done;

__device__ __forceinline__ uint32_t tf32h(float v){
  uint32_t r; asm("cvt.rna.tf32.f32 %0, %1;" : "=r"(r) : "f"(v)); return r;
}
__device__ __forceinline__ void mma_tf32(float* d, const uint32_t* a, const uint32_t* b, const float* c){
  asm volatile("mma.sync.aligned.m16n8k8.row.col.f32.tf32.tf32.f32 "
    "{%0,%1,%2,%3},{%4,%5,%6,%7},{%8,%9},{%10,%11,%12,%13};"
    : "=f"(d[0]),"=f"(d[1]),"=f"(d[2]),"=f"(d[3])
    : "r"(a[0]),"r"(a[1]),"r"(a[2]),"r"(a[3]), "r"(b[0]),"r"(b[1]),
      "f"(c[0]),"f"(c[1]),"f"(c[2]),"f"(c[3]));
}
__device__ __forceinline__ void lds64(uint32_t& x, uint32_t& y, uint32_t a){
  asm volatile("ld.shared.v2.b32 {%0,%1},[%2];" : "=r"(x), "=r"(y) : "r"(a));
}
__device__ __forceinline__ uint32_t smem_u32(const void* p){
  uint32_t a; asm("{ .reg .u64 t; cvta.to.shared.u64 t, %1; cvt.u32.u64 %0, t; }" : "=r"(a) : "l"(p));
  return a;
}
// position of k within permuted 8-chunk: [k0,k4,k1,k5,k2,k6,k3,k7]
__device__ __forceinline__ int pperm(int k){
  int km = k & 7; return (k & ~7) + ((km < 4) ? 2*km : 2*(km-4)+1);
}

__global__ void __launch_bounds__(512,1) vq_main(const float* __restrict__ x,
                                                 const float* __restrict__ emb){
  extern __shared__ float sm[];
  const uint32_t sbase = smem_u32(sm);
  const int tid = threadIdx.x, lane = tid & 31;
  const int q = lane & 3, r0 = lane >> 2;

  // build codebook h/l tf32 splits in smem
  for (int k = tid; k < 1024; k += 512){
    float e[Dd]; float nh;
    if (k < Kk){
      float s = 0.f;
      #pragma unroll
      for (int d = 0; d < Dd; d++){ e[d] = __ldg(emb + k*Dd + d); s = fmaf(e[d], e[d], s); }
      nh = -0.5f*s;
    } else {
      #pragma unroll
      for (int d = 0; d < Dd; d++) e[d] = 0.f;
      nh = -1e30f;
    }
    uint32_t* row = (uint32_t*)(sm + k*ROWW);
    #pragma unroll
    for (int kk = 0; kk < 24; kk++){
      float v = (kk < Dd) ? e[kk] : ((kk == Dd) ? nh : 0.f);
      uint32_t h = tf32h(v);
      float lres = v - __uint_as_float(h);
      row[pperm(kk)]      = h;
      row[24 + pperm(kk)] = tf32h(lres);
    }
  }
  __syncthreads();

  int u = blockIdx.x*16 + (tid >> 5);
  while (u < NUNITS){
    // A fragments: rows r0, r0+8 of this 16-point tile; k = q + 4m, m=0..5
    uint32_t ah[3][4], al[3][4];
    {
      const int n0 = u*16 + r0, n1 = n0 + 8;
      const float* p0 = x + (size_t)(n0 >> 12)*(Dd*Ll) + (n0 & (Ll-1));
      const float* p1 = x + (size_t)(n1 >> 12)*(Dd*Ll) + (n1 & (Ll-1));
      #pragma unroll
      for (int m = 0; m < 6; m++){
        const int k = q + 4*m;
        float v0 = (k < Dd) ? __ldg(p0 + k*Ll) : ((k == Dd) ? 1.f : 0.f);
        float v1 = (k < Dd) ? __ldg(p1 + k*Ll) : ((k == Dd) ? 1.f : 0.f);
        const int c = m >> 1, hi = (m & 1) ? 2 : 0;
        uint32_t h0 = tf32h(v0), h1 = tf32h(v1);
        ah[c][hi] = h0; ah[c][hi+1] = h1;
        al[c][hi]   = tf32h(v0 - __uint_as_float(h0));
        al[c][hi+1] = tf32h(v1 - __uint_as_float(h1));
      }
    }

    float best0 = -3.4e38f, best1 = -3.4e38f;
    int   idx0 = 0, idx1 = 0;
    const float z[4] = {0.f, 0.f, 0.f, 0.f};

    #pragma unroll 1
    for (int nb = 0; nb < 128; nb++){
      const uint32_t rb = sbase + ((nb*8 + r0)*ROWW + 2*q)*4;
      uint32_t bh[3][2], bl[3][2];
      #pragma unroll
      for (int c = 0; c < 3; c++){
        lds64(bh[c][0], bh[c][1], rb + c*32);
        lds64(bl[c][0], bl[c][1], rb + 96 + c*32);
      }
      // 3 independent accumulation chains (depth 3 each) -> ILP for the tensor pipe
      float dA[4], dB[4], dC[4];
      mma_tf32(dA, ah[0], bh[0], z);
      mma_tf32(dB, ah[0], bl[0], z);
      mma_tf32(dC, al[0], bh[0], z);
      mma_tf32(dA, ah[1], bh[1], dA);
      mma_tf32(dB, ah[1], bl[1], dB);
      mma_tf32(dC, al[1], bh[1], dC);
      mma_tf32(dA, ah[2], bh[2], dA);
      mma_tf32(dB, ah[2], bl[2], dB);
      mma_tf32(dC, al[2], bh[2], dC);
      float d4[4];
      #pragma unroll
      for (int j = 0; j < 4; j++) d4[j] = dA[j] + (dB[j] + dC[j]);

      const int c0 = nb*8 + 2*q;
      if (d4[0] > best0){ best0 = d4[0]; idx0 = c0; }
      if (d4[1] > best0){ best0 = d4[1]; idx0 = c0+1; }
      if (d4[2] > best1){ best1 = d4[2]; idx1 = c0; }
      if (d4[3] > best1){ best1 = d4[3]; idx1 = c0+1; }
    }

    // reduce across the 4 lanes sharing each row
    #pragma unroll
    for (int off = 1; off <= 2; off <<= 1){
      float s0 = __shfl_xor_sync(0xFFFFFFFFu, best0, off);
      int   i0 = __shfl_xor_sync(0xFFFFFFFFu, idx0,  off);
      if (s0 > best0 || (s0 == best0 && i0 < idx0)){ best0 = s0; idx0 = i0; }
      float s1 = __shfl_xor_sync(0xFFFFFFFFu, best1, off);
      int   i1 = __shfl_xor_sync(0xFFFFFFFFu, idx1,  off);
      if (s1 > best1 || (s1 == best1 && i1 < idx1)){ best1 = s1; idx1 = i1; }
    }
    if (q == 0){
      g_idx[u*16 + r0]     = idx0;
      g_idx[u*16 + r0 + 8] = idx1;
    }

    if (lane == 0) u = NWARPS + atomicAdd(&g_work, 1);
    u = __shfl_sync(0xFFFFFFFFu, u, 0);
  }
}

__global__ void __launch_bounds__(256) vq_fin(const float* __restrict__ x,
                                              const float* __restrict__ emb,
                                              float* __restrict__ out, int out_size){
  __shared__ int sh[Kk];
  __shared__ float swr[8];
  __shared__ int slast;
  const int tid = threadIdx.x;
  for (int i = tid; i < Kk; i += 256) sh[i] = 0;
  __syncthreads();

  const int n = blockIdx.x*256 + tid;
  const int code = g_idx[n];

  const int bb = n >> 12, l = n & (Ll-1);
  const float* xp = x + (size_t)bb*(Dd*Ll) + l;
  float xv[Dd], qv[Dd];
  #pragma unroll
  for (int d = 0; d < Dd; d++){ xv[d] = __ldg(xp + d*Ll); qv[d] = __ldg(emb + code*Dd + d); }
  float* op = out + (size_t)bb*(Dd*Ll) + l;
  #pragma unroll
  for (int d = 0; d < Dd; d++) op[d*Ll] = xv[d] + (qv[d] - xv[d]);
  atomicAdd(&sh[code], 1);

  float mx = xv[0], mq = qv[0];
  #pragma unroll
  for (int d = 1; d < Dd; d++){ mx = fmaxf(mx, xv[d]); mq = fmaxf(mq, qv[d]); }
  float Sx = 0.f, Sq = 0.f, A = 0.f, Cr = 0.f;
  #pragma unroll
  for (int d = 0; d < Dd; d++){
    float xs = xv[d] - mx;
    float ex = __expf(xs), eq = __expf(qv[d] - mq);
    Sx += ex; Sq += eq;
    A  = fmaf(ex, xs, A);
    Cr = fmaf(ex, eq, Cr);
  }
  float kl = A/Sx - __logf(Sx) - Cr/(Sx*Sq);

  #pragma unroll
  for (int off = 16; off; off >>= 1) kl += __shfl_xor_sync(0xFFFFFFFFu, kl, off);
  if ((tid & 31) == 0) swr[tid >> 5] = kl;
  __syncthreads();
  if (tid == 0){
    float s = 0.f;
    #pragma unroll
    for (int i = 0; i < 8; i++) s += swr[i];
    atomicAdd(&g_kl, s);
  }
  for (int i = tid; i < Kk; i += 256){ int c = sh[i]; if (c) atomicAdd(&g_hist[i], c); }

  __threadfence();
  __syncthreads();
  if (tid == 0) slast = (atomicAdd(&g_done, 1) == FINB - 1);
  __syncthreads();
  if (slast){
    float s = 0.f;
    for (int k = tid; k < Kk; k += 256){
      float a = (float)(*(volatile int*)&g_hist[k]) * (1.f/(float)Nn);
      s += a * logf(a + 1e-10f);
      g_hist[k] = 0;
    }
    #pragma unroll
    for (int off = 16; off; off >>= 1) s += __shfl_xor_sync(0xFFFFFFFFu, s, off);
    if ((tid & 31) == 0) swr[tid >> 5] = s;
    __syncthreads();
    if (tid == 0){
      float t = 0.f;
      #pragma unroll
      for (int i = 0; i < 8; i++) t += swr[i];
      if (out_size >= NDLs + 2){
        out[NDLs]     = 0.1f * ((*(volatile float*)&g_kl) / (float)Bb);
        out[NDLs + 1] = expf(-t);
      }
      g_kl = 0.f; g_done = 0; g_work = 0;
    }
  }
}

extern "C" void kernel_launch(void* const* d_in, const int* in_sizes, int n_in,
                              void* d_out, int out_size){
  const float* x   = (const float*)d_in[0];
  const float* emb = (const float*)d_in[1];
  float* out = (float*)d_out;
  cudaFuncSetAttribute(vq_main, cudaFuncAttributeMaxDynamicSharedMemorySize, SMEM_BYTES);
  vq_main<<<148, 512, SMEM_BYTES>>>(x, emb);
  vq_fin<<<FINB, 256>>>(x, emb, out, out_size);
}

// round 8
// speedup vs baseline: 1.2943x; 1.0985x over previous
#include <cuda_runtime.h>
#include <cstdint>

#define Bb 32
#define Dd 20
#define Ll 4096
#define Kk 1000
#define Nn (Bb*Ll)
#define NDLs (Bb*Dd*Ll)
#define NUNITS (Nn/16)          // 8192 m16 tiles
#define NBLK 148
#define WPB 24
#define NTHR (WPB*32)           // 768
#define NWARPS (NBLK*WPB)       // 3552
#define HWORDS (1024*24)
#define SMEM_BYTES (2*HWORDS*4) // 196608 B

__device__ int   g_work;
__device__ float g_kl;
__device__ int   g_hist[Kk];
__device__ int   g_done;

__device__ __forceinline__ uint32_t tf32h(float v){
  uint32_t r; asm("cvt.rna.tf32.f32 %0, %1;" : "=r"(r) : "f"(v)); return r;
}
__device__ __forceinline__ void mma_tf32(float* d, const uint32_t* a, const uint32_t* b, const float* c){
  asm volatile("mma.sync.aligned.m16n8k8.row.col.f32.tf32.tf32.f32 "
    "{%0,%1,%2,%3},{%4,%5,%6,%7},{%8,%9},{%10,%11,%12,%13};"
    : "=f"(d[0]),"=f"(d[1]),"=f"(d[2]),"=f"(d[3])
    : "r"(a[0]),"r"(a[1]),"r"(a[2]),"r"(a[3]), "r"(b[0]),"r"(b[1]),
      "f"(c[0]),"f"(c[1]),"f"(c[2]),"f"(c[3]));
}
__device__ __forceinline__ void lds64(uint32_t& x, uint32_t& y, uint32_t a){
  asm volatile("ld.shared.v2.b32 {%0,%1},[%2];" : "=r"(x), "=r"(y) : "r"(a));
}
__device__ __forceinline__ uint32_t smem_u32(const void* p){
  uint32_t a; asm("{ .reg .u64 t; cvta.to.shared.u64 t, %1; cvt.u32.u64 %0, t; }" : "=r"(a) : "l"(p));
  return a;
}
// position of k within permuted 8-chunk: [k0,k4,k1,k5,k2,k6,k3,k7]
__device__ __forceinline__ int pperm(int k){
  int km = k & 7; return (k & ~7) + ((km < 4) ? 2*km : 2*(km-4)+1);
}

__global__ void __launch_bounds__(NTHR,1) vq_main(const float* __restrict__ x,
                                                  const float* __restrict__ emb,
                                                  float* __restrict__ out, int out_size){
  extern __shared__ float sm[];
  float* Hs = sm;
  float* Ls = sm + HWORDS;
  __shared__ float swr[WPB];
  __shared__ int slast;
  const uint32_t sbase = smem_u32(sm);
  const uint32_t Hb = sbase, Lb = sbase + HWORDS*4;
  const int tid = threadIdx.x, lane = tid & 31, wid = tid >> 5;
  const int q = lane & 3, r0 = lane >> 2;

  // build codebook h/l tf32 splits: two packed regions, row stride 24 words (conflict-free)
  for (int k = tid; k < 1024; k += NTHR){
    float e[Dd]; float nh;
    if (k < Kk){
      float s = 0.f;
      #pragma unroll
      for (int d = 0; d < Dd; d++){ e[d] = __ldg(emb + k*Dd + d); s = fmaf(e[d], e[d], s); }
      nh = -0.5f*s;
    } else {
      #pragma unroll
      for (int d = 0; d < Dd; d++) e[d] = 0.f;
      nh = -1e30f;
    }
    #pragma unroll
    for (int kk = 0; kk < 24; kk++){
      float v = (kk < Dd) ? e[kk] : ((kk == Dd) ? nh : 0.f);
      uint32_t h = tf32h(v);
      Hs[k*24 + pperm(kk)] = __uint_as_float(h);
      Ls[k*24 + pperm(kk)] = __uint_as_float(tf32h(v - __uint_as_float(h)));
    }
  }
  __syncthreads();

  float klacc = 0.f;
  int u = blockIdx.x*WPB + wid;
  while (u < NUNITS){
    // A fragments: rows r0, r0+8; k = q + 4m, m = 0..5
    uint32_t ah[3][4], al[3][4];
    {
      const int n0 = u*16 + r0, n1 = n0 + 8;
      const float* p0 = x + (size_t)(n0 >> 12)*(Dd*Ll) + (n0 & (Ll-1));
      const float* p1 = x + (size_t)(n1 >> 12)*(Dd*Ll) + (n1 & (Ll-1));
      #pragma unroll
      for (int m = 0; m < 6; m++){
        const int k = q + 4*m;
        float v0 = (k < Dd) ? __ldg(p0 + k*Ll) : ((k == Dd) ? 1.f : 0.f);
        float v1 = (k < Dd) ? __ldg(p1 + k*Ll) : ((k == Dd) ? 1.f : 0.f);
        const int c = m >> 1, hi = (m & 1) ? 2 : 0;
        uint32_t h0 = tf32h(v0), h1 = tf32h(v1);
        ah[c][hi] = h0; ah[c][hi+1] = h1;
        al[c][hi]   = tf32h(v0 - __uint_as_float(h0));
        al[c][hi+1] = tf32h(v1 - __uint_as_float(h1));
      }
    }

    float best0 = -3.4e38f, best1 = -3.4e38f;
    int   idx0 = 0, idx1 = 0;
    const float z[4] = {0.f, 0.f, 0.f, 0.f};

    #pragma unroll 1
    for (int nb = 0; nb < 128; nb++){
      const uint32_t rwo = ((nb*8 + r0)*24 + 2*q)*4;   // row word offset (bytes)
      uint32_t bh[3][2], bl[3][2];
      #pragma unroll
      for (int c = 0; c < 3; c++){
        lds64(bh[c][0], bh[c][1], Hb + rwo + c*32);
        lds64(bl[c][0], bl[c][1], Lb + rwo + c*32);
      }
      float dA[4], dB[4], dC[4];
      mma_tf32(dA, ah[0], bh[0], z);
      mma_tf32(dB, ah[0], bl[0], z);
      mma_tf32(dC, al[0], bh[0], z);
      mma_tf32(dA, ah[1], bh[1], dA);
      mma_tf32(dB, ah[1], bl[1], dB);
      mma_tf32(dC, al[1], bh[1], dC);
      mma_tf32(dA, ah[2], bh[2], dA);
      mma_tf32(dB, ah[2], bl[2], dB);
      mma_tf32(dC, al[2], bh[2], dC);
      float d4[4];
      #pragma unroll
      for (int j = 0; j < 4; j++) d4[j] = dA[j] + (dB[j] + dC[j]);

      const int c0 = nb*8 + 2*q;
      if (d4[0] > best0){ best0 = d4[0]; idx0 = c0; }
      if (d4[1] > best0){ best0 = d4[1]; idx0 = c0+1; }
      if (d4[2] > best1){ best1 = d4[2]; idx1 = c0; }
      if (d4[3] > best1){ best1 = d4[3]; idx1 = c0+1; }
    }

    // reduce across the 4 lanes sharing each row
    #pragma unroll
    for (int off = 1; off <= 2; off <<= 1){
      float s0 = __shfl_xor_sync(0xFFFFFFFFu, best0, off);
      int   i0 = __shfl_xor_sync(0xFFFFFFFFu, idx0,  off);
      if (s0 > best0 || (s0 == best0 && i0 < idx0)){ best0 = s0; idx0 = i0; }
      float s1 = __shfl_xor_sync(0xFFFFFFFFu, best1, off);
      int   i1 = __shfl_xor_sync(0xFFFFFFFFu, idx1,  off);
      if (s1 > best1 || (s1 == best1 && i1 < idx1)){ best1 = s1; idx1 = i1; }
    }
    // distribute: lane j<16 gets code for point u*16+j
    const int src = (lane & 7)*4;
    const int c0 = __shfl_sync(0xFFFFFFFFu, idx0, src);
    const int c1 = __shfl_sync(0xFFFFFFFFu, idx1, src);

    if (lane < 16){
      const int code = (lane < 8) ? c0 : c1;
      const int n = u*16 + lane;
      const int bb = n >> 12, l = n & (Ll-1);
      const float* xp = x + (size_t)bb*(Dd*Ll) + l;
      float* op = out + (size_t)bb*(Dd*Ll) + l;
      float xv[Dd], qv[Dd];
      #pragma unroll
      for (int d = 0; d < Dd; d++){
        xv[d] = __ldg(xp + d*Ll);
        const int pp = code*24 + pperm(d);
        qv[d] = Hs[pp] + Ls[pp];
      }
      #pragma unroll
      for (int d = 0; d < Dd; d++) op[d*Ll] = xv[d] + (qv[d] - xv[d]);
      atomicAdd(&g_hist[code], 1);

      float mx = xv[0], mq = qv[0];
      #pragma unroll
      for (int d = 1; d < Dd; d++){ mx = fmaxf(mx, xv[d]); mq = fmaxf(mq, qv[d]); }
      float Sx = 0.f, Sq = 0.f, A = 0.f, Cr = 0.f;
      #pragma unroll
      for (int d = 0; d < Dd; d++){
        float xs = xv[d] - mx;
        float ex = __expf(xs), eq = __expf(qv[d] - mq);
        Sx += ex; Sq += eq;
        A  = fmaf(ex, xs, A);
        Cr = fmaf(ex, eq, Cr);
      }
      klacc += A/Sx - __logf(Sx) - Cr/(Sx*Sq);
    }

    if (lane == 0) u = NWARPS + atomicAdd(&g_work, 1);
    u = __shfl_sync(0xFFFFFFFFu, u, 0);
  }

  // block-level KL reduction, one atomic per block
  #pragma unroll
  for (int off = 16; off; off >>= 1) klacc += __shfl_xor_sync(0xFFFFFFFFu, klacc, off);
  if (lane == 0) swr[wid] = klacc;
  __syncthreads();
  if (tid == 0){
    float s = 0.f;
    #pragma unroll
    for (int w = 0; w < WPB; w++) s += swr[w];
    atomicAdd(&g_kl, s);
  }

  __threadfence();
  __syncthreads();
  if (tid == 0) slast = (atomicAdd(&g_done, 1) == NBLK - 1);
  __syncthreads();
  if (slast){
    float s = 0.f;
    for (int k = tid; k < Kk; k += NTHR){
      float a = (float)(*(volatile int*)&g_hist[k]) * (1.f/(float)Nn);
      s += a * logf(a + 1e-10f);
      g_hist[k] = 0;
    }
    #pragma unroll
    for (int off = 16; off; off >>= 1) s += __shfl_xor_sync(0xFFFFFFFFu, s, off);
    if (lane == 0) swr[wid] = s;
    __syncthreads();
    if (tid == 0){
      float t = 0.f;
      #pragma unroll
      for (int w = 0; w < WPB; w++) t += swr[w];
      if (out_size >= NDLs + 2){
        out[NDLs]     = 0.1f * ((*(volatile float*)&g_kl) / (float)Bb);
        out[NDLs + 1] = expf(-t);
      }
      g_kl = 0.f; g_done = 0; g_work = 0;
    }
  }
}

extern "C" void kernel_launch(void* const* d_in, const int* in_sizes, int n_in,
                              void* d_out, int out_size){
  const float* x   = (const float*)d_in[0];
  const float* emb = (const float*)d_in[1];
  float* out = (float*)d_out;
  cudaFuncSetAttribute(vq_main, cudaFuncAttributeMaxDynamicSharedMemorySize, SMEM_BYTES);
  vq_main<<<NBLK, NTHR, SMEM_BYTES>>>(x, emb, out, out_size);
}